// round 4
// baseline (speedup 1.0000x reference)
#include <cuda_runtime.h>
#include <cuda_bf16.h>
#include <cstdint>

// AtomTypeLinear: out[n,:] = x[n,:] @ M[type[n]] + b[type[n]]
// N=100000, IN=OUT=64, NUM_TYPES=64, fp32.
//
// 2-kernel pipeline:
//   k_sort: fused histogram + software grid barrier + scatter (counting sort)
//   k_gemm: per-type GEMM, mma.sync.m16n8k8 tf32, B-fragments hoisted to
//           registers (zero smem traffic in the mainloop)

#define NUM_TYPES 64
#define MAX_N     102400
#define NB        128     // sort blocks; must all be co-resident (128 < 148 SMs)

__device__ int g_partial[NB][NUM_TYPES];
__device__ int g_offsets[NUM_TYPES + 1];
__device__ int g_perm[MAX_N];
__device__ unsigned g_cnt = 0;
__device__ unsigned g_gen = 0;

// ---------------------------------------------------------------------------
__device__ __forceinline__ uint32_t f2tf32(float f) {
    uint32_t r;
    asm("cvt.rna.tf32.f32 %0, %1;" : "=r"(r) : "f"(f));
    return r;
}

__device__ __forceinline__ void mma_tf32(float* c, const uint32_t* a,
                                         uint32_t b0, uint32_t b1) {
    asm volatile(
        "mma.sync.aligned.m16n8k8.row.col.f32.tf32.tf32.f32 "
        "{%0,%1,%2,%3}, {%4,%5,%6,%7}, {%8,%9}, {%0,%1,%2,%3};"
        : "+f"(c[0]), "+f"(c[1]), "+f"(c[2]), "+f"(c[3])
        : "r"(a[0]), "r"(a[1]), "r"(a[2]), "r"(a[3]), "r"(b0), "r"(b1));
}

// Sense-reversing grid barrier. Safe: all NB blocks are resident in wave 1.
// g_cnt returns to 0 every barrier; g_gen increases monotonically across
// graph replays (no reset needed -> deterministic, replay-safe).
__device__ __forceinline__ void grid_barrier() {
    __threadfence();
    __syncthreads();
    if (threadIdx.x == 0) {
        unsigned gen = atomicAdd(&g_gen, 0u);
        __threadfence();
        if (atomicAdd(&g_cnt, 1u) == (unsigned)NB - 1u) {
            atomicExch(&g_cnt, 0u);
            __threadfence();
            atomicAdd(&g_gen, 1u);
        } else {
            while (atomicAdd(&g_gen, 0u) == gen) {}
        }
    }
    __syncthreads();
}

// ---------------------------------------------------------------------------
// Kernel 1: fused counting sort.
//   phase A: dtype detect + per-block histogram (vectorized int4 reads)
//   barrier
//   phase B: per-block cursor reconstruction + scatter into g_perm
// ---------------------------------------------------------------------------
__global__ void __launch_bounds__(256)
k_sort(const void* __restrict__ types, int n) {
    __shared__ int sh[NUM_TYPES];
    __shared__ int s_is64;
    __shared__ int s_wtot[4][NUM_TYPES];
    __shared__ int s_wbef[4][NUM_TYPES];
    __shared__ int s_off[NUM_TYPES];
    __shared__ int s_cursor[NUM_TYPES];

    const int tid = threadIdx.x;
    const int b   = blockIdx.x;

    if (tid < NUM_TYPES) sh[tid] = 0;
    if (tid == 0) s_is64 = 1;
    __syncthreads();
    // int64 (LE) => every odd 32-bit word of the buffer is 0 (values < 64).
    if (tid < 64) {
        int idx = 2 * tid + 1;
        if (idx < n && ((const int*)types)[idx] != 0) s_is64 = 0;
    }
    __syncthreads();
    const int is64 = s_is64;

    // element chunk per block, multiple of 4 for vector alignment
    const int chunk = (((n + NB - 1) / NB) + 3) & ~3;
    const int lo = b * chunk;
    const int hi = min(n, lo + chunk);
    const int m  = hi - lo;   // elements this block owns (may be <= 0)

    // --- phase A: histogram ---
    if (m > 0) {
        if (is64) {
            const int4* p = (const int4*)((const long long*)types + lo);
            for (int e = tid * 2; e < m; e += 512) {
                if (e + 1 < m) {
                    int4 v = p[e >> 1];
                    atomicAdd(&sh[v.x & 63], 1);
                    atomicAdd(&sh[v.z & 63], 1);
                } else {
                    int t = (int)((const long long*)types)[lo + e];
                    atomicAdd(&sh[t & 63], 1);
                }
            }
        } else {
            const int4* p = (const int4*)((const int*)types + lo);
            for (int e = tid * 4; e < m; e += 1024) {
                if (e + 3 < m) {
                    int4 v = p[e >> 2];
                    atomicAdd(&sh[v.x & 63], 1);
                    atomicAdd(&sh[v.y & 63], 1);
                    atomicAdd(&sh[v.z & 63], 1);
                    atomicAdd(&sh[v.w & 63], 1);
                } else {
                    for (int j = e; j < m; j++) {
                        int t = ((const int*)types)[lo + j];
                        atomicAdd(&sh[t & 63], 1);
                    }
                }
            }
        }
    }
    __syncthreads();
    if (tid < NUM_TYPES) g_partial[b][tid] = sh[tid];

    grid_barrier();

    // --- phase B: reconstruct cursors (4-way split over block windows) ---
    {
        const int q = tid >> 6;       // window 0..3, 32 blocks each
        const int t = tid & 63;
        int tot = 0, bef = 0;
        const int b0w = q * 32;
#pragma unroll 8
        for (int bb = b0w; bb < b0w + 32; bb++) {
            int c = g_partial[bb][t];
            tot += c;
            if (bb < b) bef += c;
        }
        s_wtot[q][t] = tot;
        s_wbef[q][t] = bef;
    }
    __syncthreads();
    if (tid < NUM_TYPES) {
        int tot = s_wtot[0][tid] + s_wtot[1][tid] + s_wtot[2][tid] + s_wtot[3][tid];
        int bef = s_wbef[0][tid] + s_wbef[1][tid] + s_wbef[2][tid] + s_wbef[3][tid];
        s_wtot[0][tid] = tot;   // reuse as totals
        s_wbef[0][tid] = bef;   // reuse as before-count
    }
    __syncthreads();
    if (tid == 0) {
        int acc = 0;
        for (int t = 0; t < NUM_TYPES; t++) {
            s_off[t] = acc;
            acc += s_wtot[0][t];
        }
    }
    __syncthreads();
    if (tid < NUM_TYPES) {
        s_cursor[tid] = s_off[tid] + s_wbef[0][tid];
        if (b == 0) g_offsets[tid] = s_off[tid];
    }
    if (b == 0 && tid == 0) g_offsets[NUM_TYPES] = n;
    __syncthreads();

    // --- scatter ---
    if (m > 0) {
        if (is64) {
            const int4* p = (const int4*)((const long long*)types + lo);
            for (int e = tid * 2; e < m; e += 512) {
                if (e + 1 < m) {
                    int4 v = p[e >> 1];
                    int p0 = atomicAdd(&s_cursor[v.x & 63], 1);
                    int p1 = atomicAdd(&s_cursor[v.z & 63], 1);
                    g_perm[p0] = lo + e;
                    g_perm[p1] = lo + e + 1;
                } else {
                    int t = (int)((const long long*)types)[lo + e];
                    g_perm[atomicAdd(&s_cursor[t & 63], 1)] = lo + e;
                }
            }
        } else {
            const int4* p = (const int4*)((const int*)types + lo);
            for (int e = tid * 4; e < m; e += 1024) {
                if (e + 3 < m) {
                    int4 v = p[e >> 2];
                    int p0 = atomicAdd(&s_cursor[v.x & 63], 1);
                    int p1 = atomicAdd(&s_cursor[v.y & 63], 1);
                    int p2 = atomicAdd(&s_cursor[v.z & 63], 1);
                    int p3 = atomicAdd(&s_cursor[v.w & 63], 1);
                    g_perm[p0] = lo + e;
                    g_perm[p1] = lo + e + 1;
                    g_perm[p2] = lo + e + 2;
                    g_perm[p3] = lo + e + 3;
                } else {
                    for (int j = e; j < m; j++) {
                        int t = ((const int*)types)[lo + j];
                        g_perm[atomicAdd(&s_cursor[t & 63], 1)] = lo + j;
                    }
                }
            }
        }
    }
}

// ---------------------------------------------------------------------------
// Kernel 2: per-type GEMM. Block = 8 warps as 4(m) x 2(n): tile m64 x n64.
// Warp tile: m16 x n32 x k64. B fragments (64 regs/thread) hoisted out of
// the tile loop -> mainloop has NO shared-memory traffic.
// ---------------------------------------------------------------------------
#define WSTR 68

__global__ void __launch_bounds__(256, 2)
k_gemm(const float* __restrict__ x, const float* __restrict__ Wm,
       const float* __restrict__ bias, float* __restrict__ out) {
    __shared__ float Ws[64][WSTR];
    __shared__ float bs[64];

    const int type = blockIdx.y;
    const int seg0 = g_offsets[type];
    const int count = g_offsets[type + 1] - seg0;
    const int ntiles = (count + 63) >> 6;
    if ((int)blockIdx.x >= ntiles) return;

    // Stage W[type] into smem, pre-converted to tf32 bits (coalesced DRAM/L2).
    const float* Wt = Wm + type * 4096;
    for (int i = threadIdx.x; i < 4096; i += 256) {
        int k = i >> 6, nn = i & 63;
        Ws[k][nn] = __uint_as_float(f2tf32(Wt[i]));
    }
    if (threadIdx.x < 64) bs[threadIdx.x] = bias[type * 64 + threadIdx.x];
    __syncthreads();

    const int warp = threadIdx.x >> 5;
    const int lane = threadIdx.x & 31;
    const int wm = warp >> 1;          // 0..3 : m position
    const int wn = warp & 1;           // 0..1 : n position
    const int g  = lane >> 2;          // 0..7
    const int tg = lane & 3;           // 0..3

    // Hoist B fragments into registers (loop-invariant across tiles).
    uint32_t B0[8][4], B1[8][4];
#pragma unroll
    for (int ks = 0; ks < 8; ks++) {
#pragma unroll
        for (int nc = 0; nc < 4; nc++) {
            int col = wn * 32 + nc * 8 + g;
            B0[ks][nc] = __float_as_uint(Ws[ks * 8 + tg    ][col]);
            B1[ks][nc] = __float_as_uint(Ws[ks * 8 + tg + 4][col]);
        }
    }

    for (int tile = blockIdx.x; tile < ntiles; tile += gridDim.x) {
        const int lr0 = tile * 64 + wm * 16 + g;
        const int lr1 = lr0 + 8;
        const int row0 = (lr0 < count) ? g_perm[seg0 + lr0] : -1;
        const int row1 = (lr1 < count) ? g_perm[seg0 + lr1] : -1;
        const bool v0 = (row0 >= 0), v1 = (row1 >= 0);
        const float* x0 = x + (v0 ? (size_t)row0 * 64 : 0);
        const float* x1 = x + (v1 ? (size_t)row1 * 64 : 0);

        float acc[4][4];
#pragma unroll
        for (int nc = 0; nc < 4; nc++) {
            acc[nc][0] = 0.f; acc[nc][1] = 0.f;
            acc[nc][2] = 0.f; acc[nc][3] = 0.f;
        }

        uint32_t Acur[4], Anxt[4];
        {
            Acur[0] = f2tf32(v0 ? __ldg(&x0[tg])     : 0.f);
            Acur[1] = f2tf32(v1 ? __ldg(&x1[tg])     : 0.f);
            Acur[2] = f2tf32(v0 ? __ldg(&x0[tg + 4]) : 0.f);
            Acur[3] = f2tf32(v1 ? __ldg(&x1[tg + 4]) : 0.f);
        }
#pragma unroll
        for (int ks = 0; ks < 8; ks++) {
            if (ks < 7) {
                int c = (ks + 1) * 8 + tg;
                Anxt[0] = f2tf32(v0 ? __ldg(&x0[c])     : 0.f);
                Anxt[1] = f2tf32(v1 ? __ldg(&x1[c])     : 0.f);
                Anxt[2] = f2tf32(v0 ? __ldg(&x0[c + 4]) : 0.f);
                Anxt[3] = f2tf32(v1 ? __ldg(&x1[c + 4]) : 0.f);
            }
#pragma unroll
            for (int nc = 0; nc < 4; nc++)
                mma_tf32(acc[nc], Acur, B0[ks][nc], B1[ks][nc]);
#pragma unroll
            for (int j = 0; j < 4; j++) Acur[j] = Anxt[j];
        }

#pragma unroll
        for (int nc = 0; nc < 4; nc++) {
            int col = wn * 32 + nc * 8 + tg * 2;
            float bv0 = bs[col], bv1 = bs[col + 1];
            if (v0) {
                float2 v = make_float2(acc[nc][0] + bv0, acc[nc][1] + bv1);
                *reinterpret_cast<float2*>(out + (size_t)row0 * 64 + col) = v;
            }
            if (v1) {
                float2 v = make_float2(acc[nc][2] + bv0, acc[nc][3] + bv1);
                *reinterpret_cast<float2*>(out + (size_t)row1 * 64 + col) = v;
            }
        }
    }
}

// ---------------------------------------------------------------------------
extern "C" void kernel_launch(void* const* d_in, const int* in_sizes, int n_in,
                              void* d_out, int out_size) {
    const float* x      = (const float*)d_in[0];
    const void*  types  = d_in[1];
    const float* matrix = (const float*)d_in[2];
    const float* bias   = (const float*)d_in[3];
    float*       out    = (float*)d_out;
    const int n = in_sizes[1];

    k_sort<<<NB, 256>>>(types, n);
    dim3 grid(16, NUM_TYPES);
    k_gemm<<<grid, 256>>>(x, matrix, bias, out);
}

// round 5
// speedup vs baseline: 1.4482x; 1.4482x over previous
#include <cuda_runtime.h>
#include <cuda_bf16.h>
#include <cstdint>

// AtomTypeLinear: out[n,:] = x[n,:] @ M[type[n]] + b[type[n]]
// N=100000, IN=OUT=64, NUM_TYPES=64, fp32.
//
// k_sort: fused histogram + grid barrier + scatter (counting sort)
// k_gemm: per-type GEMM, mma.m16n8k8 tf32; A rows gathered via cp.async
//         double-buffered smem stages; B transposed in smem (conflict-free);
//         4 blocks/SM, single-wave grid.

#define NUM_TYPES 64
#define MAX_N     102400
#define NB        128     // sort blocks; co-resident (128 < 148 SMs)
#define WSTR      68
#define SLOTS     8

__device__ int g_partial[NB][NUM_TYPES];
__device__ int g_offsets[NUM_TYPES + 1];
__device__ int g_perm[MAX_N];
__device__ unsigned g_cnt = 0;
__device__ unsigned g_gen = 0;

// ---------------------------------------------------------------------------
__device__ __forceinline__ uint32_t f2tf32(float f) {
    uint32_t r;
    asm("cvt.rna.tf32.f32 %0, %1;" : "=r"(r) : "f"(f));
    return r;
}

__device__ __forceinline__ void mma_tf32(float* c, const uint32_t* a,
                                         uint32_t b0, uint32_t b1) {
    asm volatile(
        "mma.sync.aligned.m16n8k8.row.col.f32.tf32.tf32.f32 "
        "{%0,%1,%2,%3}, {%4,%5,%6,%7}, {%8,%9}, {%0,%1,%2,%3};"
        : "+f"(c[0]), "+f"(c[1]), "+f"(c[2]), "+f"(c[3])
        : "r"(a[0]), "r"(a[1]), "r"(a[2]), "r"(a[3]), "r"(b0), "r"(b1));
}

__device__ __forceinline__ void cp_async16(uint32_t dst, const void* src) {
    asm volatile("cp.async.ca.shared.global [%0], [%1], 16;" :: "r"(dst), "l"(src));
}
__device__ __forceinline__ void cp_commit() {
    asm volatile("cp.async.commit_group;");
}
template <int N>
__device__ __forceinline__ void cp_wait() {
    asm volatile("cp.async.wait_group %0;" :: "n"(N));
}

// Sense-reversing grid barrier; all NB blocks co-resident in wave 1.
__device__ __forceinline__ void grid_barrier() {
    __threadfence();
    __syncthreads();
    if (threadIdx.x == 0) {
        unsigned gen = atomicAdd(&g_gen, 0u);
        __threadfence();
        if (atomicAdd(&g_cnt, 1u) == (unsigned)NB - 1u) {
            atomicExch(&g_cnt, 0u);
            __threadfence();
            atomicAdd(&g_gen, 1u);
        } else {
            while (atomicAdd(&g_gen, 0u) == gen) {}
        }
    }
    __syncthreads();
}

// ---------------------------------------------------------------------------
// Kernel 1: fused counting sort (unchanged from R4).
// ---------------------------------------------------------------------------
__global__ void __launch_bounds__(256)
k_sort(const void* __restrict__ types, int n) {
    __shared__ int sh[NUM_TYPES];
    __shared__ int s_is64;
    __shared__ int s_wtot[4][NUM_TYPES];
    __shared__ int s_wbef[4][NUM_TYPES];
    __shared__ int s_off[NUM_TYPES];
    __shared__ int s_cursor[NUM_TYPES];

    const int tid = threadIdx.x;
    const int b   = blockIdx.x;

    if (tid < NUM_TYPES) sh[tid] = 0;
    if (tid == 0) s_is64 = 1;
    __syncthreads();
    if (tid < 64) {
        int idx = 2 * tid + 1;
        if (idx < n && ((const int*)types)[idx] != 0) s_is64 = 0;
    }
    __syncthreads();
    const int is64 = s_is64;

    const int chunk = (((n + NB - 1) / NB) + 3) & ~3;
    const int lo = b * chunk;
    const int hi = min(n, lo + chunk);
    const int m  = hi - lo;

    if (m > 0) {
        if (is64) {
            const int4* p = (const int4*)((const long long*)types + lo);
            for (int e = tid * 2; e < m; e += 512) {
                if (e + 1 < m) {
                    int4 v = p[e >> 1];
                    atomicAdd(&sh[v.x & 63], 1);
                    atomicAdd(&sh[v.z & 63], 1);
                } else {
                    int t = (int)((const long long*)types)[lo + e];
                    atomicAdd(&sh[t & 63], 1);
                }
            }
        } else {
            const int4* p = (const int4*)((const int*)types + lo);
            for (int e = tid * 4; e < m; e += 1024) {
                if (e + 3 < m) {
                    int4 v = p[e >> 2];
                    atomicAdd(&sh[v.x & 63], 1);
                    atomicAdd(&sh[v.y & 63], 1);
                    atomicAdd(&sh[v.z & 63], 1);
                    atomicAdd(&sh[v.w & 63], 1);
                } else {
                    for (int j = e; j < m; j++)
                        atomicAdd(&sh[((const int*)types)[lo + j] & 63], 1);
                }
            }
        }
    }
    __syncthreads();
    if (tid < NUM_TYPES) g_partial[b][tid] = sh[tid];

    grid_barrier();

    {
        const int q = tid >> 6;
        const int t = tid & 63;
        int tot = 0, bef = 0;
        const int b0w = q * 32;
#pragma unroll 8
        for (int bb = b0w; bb < b0w + 32; bb++) {
            int c = g_partial[bb][t];
            tot += c;
            if (bb < b) bef += c;
        }
        s_wtot[q][t] = tot;
        s_wbef[q][t] = bef;
    }
    __syncthreads();
    if (tid < NUM_TYPES) {
        s_wtot[0][tid] = s_wtot[0][tid] + s_wtot[1][tid] + s_wtot[2][tid] + s_wtot[3][tid];
        s_wbef[0][tid] = s_wbef[0][tid] + s_wbef[1][tid] + s_wbef[2][tid] + s_wbef[3][tid];
    }
    __syncthreads();
    if (tid == 0) {
        int acc = 0;
        for (int t = 0; t < NUM_TYPES; t++) {
            s_off[t] = acc;
            acc += s_wtot[0][t];
        }
    }
    __syncthreads();
    if (tid < NUM_TYPES) {
        s_cursor[tid] = s_off[tid] + s_wbef[0][tid];
        if (b == 0) g_offsets[tid] = s_off[tid];
    }
    if (b == 0 && tid == 0) g_offsets[NUM_TYPES] = n;
    __syncthreads();

    if (m > 0) {
        if (is64) {
            const int4* p = (const int4*)((const long long*)types + lo);
            for (int e = tid * 2; e < m; e += 512) {
                if (e + 1 < m) {
                    int4 v = p[e >> 1];
                    int p0 = atomicAdd(&s_cursor[v.x & 63], 1);
                    int p1 = atomicAdd(&s_cursor[v.z & 63], 1);
                    g_perm[p0] = lo + e;
                    g_perm[p1] = lo + e + 1;
                } else {
                    int t = (int)((const long long*)types)[lo + e];
                    g_perm[atomicAdd(&s_cursor[t & 63], 1)] = lo + e;
                }
            }
        } else {
            const int4* p = (const int4*)((const int*)types + lo);
            for (int e = tid * 4; e < m; e += 1024) {
                if (e + 3 < m) {
                    int4 v = p[e >> 2];
                    int p0 = atomicAdd(&s_cursor[v.x & 63], 1);
                    int p1 = atomicAdd(&s_cursor[v.y & 63], 1);
                    int p2 = atomicAdd(&s_cursor[v.z & 63], 1);
                    int p3 = atomicAdd(&s_cursor[v.w & 63], 1);
                    g_perm[p0] = lo + e;
                    g_perm[p1] = lo + e + 1;
                    g_perm[p2] = lo + e + 2;
                    g_perm[p3] = lo + e + 3;
                } else {
                    for (int j = e; j < m; j++) {
                        int t = ((const int*)types)[lo + j];
                        g_perm[atomicAdd(&s_cursor[t & 63], 1)] = lo + j;
                    }
                }
            }
        }
    }
}

// ---------------------------------------------------------------------------
// Kernel 2: GEMM. Block = 8 warps (4m x 2n), tile = 64 rows x 64 cols.
// A rows gathered via cp.async into double-buffered smem; W transposed
// in smem (conflict-free B fragment reads). 4 blocks/SM.
// Dynamic smem: Ws[64*WSTR] + bs[64] + sidx[2*64] + As[2*64*WSTR] = ~53KB.
// ---------------------------------------------------------------------------
#define DSMEM_BYTES ((64 * WSTR + 64 + 128 + 2 * 64 * WSTR) * 4)

__global__ void __launch_bounds__(256, 4)
k_gemm(const float* __restrict__ x, const float* __restrict__ Wm,
       const float* __restrict__ bias, float* __restrict__ out) {
    extern __shared__ float dsm[];
    float* Ws   = dsm;                       // [64][WSTR], transposed: Ws[n][k]
    float* bsm  = Ws + 64 * WSTR;            // [64]
    int*   sidx = (int*)(bsm + 64);          // [2][64]
    float* As   = (float*)(sidx + 128);      // [2][64][WSTR]

    const int type  = blockIdx.y;
    const int seg0  = g_offsets[type];
    const int count = g_offsets[type + 1] - seg0;
    const int ntiles = (count + 63) >> 6;
    if ((int)blockIdx.x >= ntiles) return;

    const int tid = threadIdx.x;
    const int c   = tid & 15;    // float4 chunk within a row
    const int j0  = tid >> 4;    // row group (16 rows per pass)

#define LOAD_STAGE(s, tile_)                                                  \
    do {                                                                      \
        float* dstb = As + (s) * 64 * WSTR;                                   \
        int t0 = (tile_) * 64;                                                \
        _Pragma("unroll")                                                     \
        for (int j = j0; j < 64; j += 16) {                                   \
            int r = t0 + j;                                                   \
            int valid = (r < count);                                          \
            int idx = valid ? __ldg(&g_perm[seg0 + r]) : 0;                   \
            if (c == 0) sidx[(s) * 64 + j] = valid ? idx : -1;                \
            uint32_t d = (uint32_t)__cvta_generic_to_shared(                  \
                dstb + j * WSTR + c * 4);                                     \
            cp_async16(d, x + (size_t)idx * 64 + c * 4);                      \
        }                                                                     \
    } while (0)

    // Stage 0 A-loads first (don't depend on smem W), then stage W + bias.
    LOAD_STAGE(0, blockIdx.x);
    cp_commit();

    const float* Wt = Wm + type * 4096;
    for (int i = tid; i < 4096; i += 256) {
        int k = i >> 6, nn = i & 63;
        Ws[nn * WSTR + k] = __uint_as_float(f2tf32(Wt[i]));
    }
    if (tid < 64) bsm[tid] = bias[type * 64 + tid];

    const int warp = tid >> 5;
    const int lane = tid & 31;
    const int wm = warp >> 1, wn = warp & 1;
    const int g  = lane >> 2, tg = lane & 3;
    const int lr0 = wm * 16 + g;

    int iter = 0;
    for (int tile = blockIdx.x; tile < ntiles; tile += gridDim.x, iter++) {
        const int s = iter & 1;
        const int nt = tile + gridDim.x;
        if (nt < ntiles) {
            LOAD_STAGE(s ^ 1, nt);
            cp_commit();
            cp_wait<1>();
        } else {
            cp_wait<0>();
        }
        __syncthreads();   // stage s data + W visible to all

        const float* A0 = As + s * 64 * WSTR + lr0 * WSTR;
        const float* A1 = A0 + 8 * WSTR;

        float acc[4][4];
#pragma unroll
        for (int nc = 0; nc < 4; nc++) {
            acc[nc][0] = 0.f; acc[nc][1] = 0.f;
            acc[nc][2] = 0.f; acc[nc][3] = 0.f;
        }

#pragma unroll
        for (int ks = 0; ks < 8; ks++) {
            uint32_t a[4];
            a[0] = f2tf32(A0[ks * 8 + tg]);
            a[1] = f2tf32(A1[ks * 8 + tg]);
            a[2] = f2tf32(A0[ks * 8 + tg + 4]);
            a[3] = f2tf32(A1[ks * 8 + tg + 4]);
#pragma unroll
            for (int nc = 0; nc < 4; nc++) {
                const float* Bc = Ws + (wn * 32 + nc * 8 + g) * WSTR;
                uint32_t b0 = __float_as_uint(Bc[ks * 8 + tg]);
                uint32_t b1 = __float_as_uint(Bc[ks * 8 + tg + 4]);
                mma_tf32(acc[nc], a, b0, b1);
            }
        }

        const int row0 = sidx[s * 64 + lr0];
        const int row1 = sidx[s * 64 + lr0 + 8];
#pragma unroll
        for (int nc = 0; nc < 4; nc++) {
            int col = wn * 32 + nc * 8 + tg * 2;
            float bv0 = bsm[col], bv1 = bsm[col + 1];
            if (row0 >= 0) {
                float2 v = make_float2(acc[nc][0] + bv0, acc[nc][1] + bv1);
                *reinterpret_cast<float2*>(out + (size_t)row0 * 64 + col) = v;
            }
            if (row1 >= 0) {
                float2 v = make_float2(acc[nc][2] + bv0, acc[nc][3] + bv1);
                *reinterpret_cast<float2*>(out + (size_t)row1 * 64 + col) = v;
            }
        }
        __syncthreads();   // all done with stage s before it is overwritten
    }
#undef LOAD_STAGE
}

// ---------------------------------------------------------------------------
extern "C" void kernel_launch(void* const* d_in, const int* in_sizes, int n_in,
                              void* d_out, int out_size) {
    const float* x      = (const float*)d_in[0];
    const void*  types  = d_in[1];
    const float* matrix = (const float*)d_in[2];
    const float* bias   = (const float*)d_in[3];
    float*       out    = (float*)d_out;
    const int n = in_sizes[1];

    // Opt-in for >48KB dynamic smem (idempotent; first call happens on the
    // correctness run outside graph capture).
    cudaFuncSetAttribute(k_gemm, cudaFuncAttributeMaxDynamicSharedMemorySize,
                         DSMEM_BYTES);

    k_sort<<<NB, 256>>>(types, n);
    dim3 grid(SLOTS, NUM_TYPES);
    k_gemm<<<grid, 256, DSMEM_BYTES>>>(x, matrix, bias, out);
}

// round 6
// speedup vs baseline: 1.6495x; 1.1390x over previous
#include <cuda_runtime.h>
#include <cuda_bf16.h>
#include <cstdint>

// AtomTypeLinear: out[n,:] = x[n,:] @ M[type[n]] + b[type[n]]
// N=100000, IN=OUT=64, NUM_TYPES=64, fp32.
//
// k_sort: fused histogram + grid barrier + scatter (counting sort)
//         + W transpose/convert to tf32 (g_wtf[type][n][k])
// k_gemm: per-type GEMM, mma.m16n8k8 tf32. A gathered via cp.async double
//         buffer; W via cp.async from pre-converted g_wtf. All fragment
//         reads are conflict-free LDS.64 via k-slot permutation.

#define NUM_TYPES 64
#define MAX_N     102400
#define NB        128     // sort blocks; co-resident (128 < 148 SMs)
#define WSTR      72      // 72 mod 32 = 8 -> conflict-free float2 frag reads
#define SLOTS     9

__device__ int g_partial[NB][NUM_TYPES];
__device__ int g_offsets[NUM_TYPES + 1];
__device__ int g_perm[MAX_N];
__device__ unsigned g_cnt = 0;
__device__ unsigned g_gen = 0;
__device__ uint32_t g_wtf[NUM_TYPES * 4096];   // tf32 bits, [type][n][k]

// ---------------------------------------------------------------------------
__device__ __forceinline__ uint32_t f2tf32(float f) {
    uint32_t r;
    asm("cvt.rna.tf32.f32 %0, %1;" : "=r"(r) : "f"(f));
    return r;
}

__device__ __forceinline__ void mma_tf32(float* c, const uint32_t* a,
                                         uint32_t b0, uint32_t b1) {
    asm volatile(
        "mma.sync.aligned.m16n8k8.row.col.f32.tf32.tf32.f32 "
        "{%0,%1,%2,%3}, {%4,%5,%6,%7}, {%8,%9}, {%0,%1,%2,%3};"
        : "+f"(c[0]), "+f"(c[1]), "+f"(c[2]), "+f"(c[3])
        : "r"(a[0]), "r"(a[1]), "r"(a[2]), "r"(a[3]), "r"(b0), "r"(b1));
}

__device__ __forceinline__ void cp_async16(uint32_t dst, const void* src) {
    asm volatile("cp.async.ca.shared.global [%0], [%1], 16;" :: "r"(dst), "l"(src));
}
__device__ __forceinline__ void cp_commit() {
    asm volatile("cp.async.commit_group;");
}
template <int N>
__device__ __forceinline__ void cp_wait() {
    asm volatile("cp.async.wait_group %0;" :: "n"(N));
}

// Sense-reversing grid barrier; all NB blocks co-resident in wave 1.
__device__ __forceinline__ void grid_barrier() {
    __threadfence();
    __syncthreads();
    if (threadIdx.x == 0) {
        unsigned gen = atomicAdd(&g_gen, 0u);
        __threadfence();
        if (atomicAdd(&g_cnt, 1u) == (unsigned)NB - 1u) {
            atomicExch(&g_cnt, 0u);
            __threadfence();
            atomicAdd(&g_gen, 1u);
        } else {
            while (atomicAdd(&g_gen, 0u) == gen) {}
        }
    }
    __syncthreads();
}

// ---------------------------------------------------------------------------
// Kernel 1: fused counting sort + W transpose/convert.
// ---------------------------------------------------------------------------
__global__ void __launch_bounds__(256)
k_sort(const void* __restrict__ types, const float* __restrict__ Wm, int n) {
    __shared__ int sh[NUM_TYPES];
    __shared__ int s_is64;
    __shared__ int s_wtot[4][NUM_TYPES];
    __shared__ int s_wbef[4][NUM_TYPES];
    __shared__ int s_off[NUM_TYPES];
    __shared__ int s_cursor[NUM_TYPES];
    __shared__ float sW[32][65];

    const int tid = threadIdx.x;
    const int b   = blockIdx.x;

    if (tid < NUM_TYPES) sh[tid] = 0;
    if (tid == 0) s_is64 = 1;
    __syncthreads();
    // int64 (LE) => every odd 32-bit word is 0 (values < 64).
    if (tid < 64) {
        int idx = 2 * tid + 1;
        if (idx < n && ((const int*)types)[idx] != 0) s_is64 = 0;
    }
    __syncthreads();
    const int is64 = s_is64;

    const int chunk = (((n + NB - 1) / NB) + 3) & ~3;
    const int lo = b * chunk;
    const int hi = min(n, lo + chunk);
    const int m  = hi - lo;

    // --- phase A: histogram ---
    if (m > 0) {
        if (is64) {
            const int4* p = (const int4*)((const long long*)types + lo);
            for (int e = tid * 2; e < m; e += 512) {
                if (e + 1 < m) {
                    int4 v = p[e >> 1];
                    atomicAdd(&sh[v.x & 63], 1);
                    atomicAdd(&sh[v.z & 63], 1);
                } else {
                    int t = (int)((const long long*)types)[lo + e];
                    atomicAdd(&sh[t & 63], 1);
                }
            }
        } else {
            const int4* p = (const int4*)((const int*)types + lo);
            for (int e = tid * 4; e < m; e += 1024) {
                if (e + 3 < m) {
                    int4 v = p[e >> 2];
                    atomicAdd(&sh[v.x & 63], 1);
                    atomicAdd(&sh[v.y & 63], 1);
                    atomicAdd(&sh[v.z & 63], 1);
                    atomicAdd(&sh[v.w & 63], 1);
                } else {
                    for (int j = e; j < m; j++)
                        atomicAdd(&sh[((const int*)types)[lo + j] & 63], 1);
                }
            }
        }
    }
    __syncthreads();
    if (tid < NUM_TYPES) g_partial[b][tid] = sh[tid];

    // --- W transpose + tf32 convert (overlaps barrier wait of others) ---
    // Block b handles type b>>1, k rows [k0, k0+32).
    {
        const int ty = b >> 1;
        const int k0 = (b & 1) * 32;
        const float* Wt = Wm + ty * 4096 + k0 * 64;   // [32 rows][64 n]
        for (int idx = tid; idx < 2048; idx += 256)
            sW[idx >> 6][idx & 63] = Wt[idx];          // coalesced read
        __syncthreads();
        for (int idx = tid; idx < 2048; idx += 256) {
            int nn = idx >> 5, kk = idx & 31;
            g_wtf[ty * 4096 + nn * 64 + k0 + kk] = f2tf32(sW[kk][nn]);
        }
    }

    grid_barrier();

    // --- phase B: reconstruct cursors ---
    {
        const int q = tid >> 6;
        const int t = tid & 63;
        int tot = 0, bef = 0;
        const int b0w = q * 32;
#pragma unroll 8
        for (int bb = b0w; bb < b0w + 32; bb++) {
            int c = g_partial[bb][t];
            tot += c;
            if (bb < b) bef += c;
        }
        s_wtot[q][t] = tot;
        s_wbef[q][t] = bef;
    }
    __syncthreads();
    if (tid < NUM_TYPES) {
        s_wtot[0][tid] = s_wtot[0][tid] + s_wtot[1][tid] + s_wtot[2][tid] + s_wtot[3][tid];
        s_wbef[0][tid] = s_wbef[0][tid] + s_wbef[1][tid] + s_wbef[2][tid] + s_wbef[3][tid];
    }
    __syncthreads();
    if (tid == 0) {
        int acc = 0;
        for (int t = 0; t < NUM_TYPES; t++) {
            s_off[t] = acc;
            acc += s_wtot[0][t];
        }
    }
    __syncthreads();
    if (tid < NUM_TYPES) {
        s_cursor[tid] = s_off[tid] + s_wbef[0][tid];
        if (b == 0) g_offsets[tid] = s_off[tid];
    }
    if (b == 0 && tid == 0) g_offsets[NUM_TYPES] = n;
    __syncthreads();

    // --- scatter ---
    if (m > 0) {
        if (is64) {
            const int4* p = (const int4*)((const long long*)types + lo);
            for (int e = tid * 2; e < m; e += 512) {
                if (e + 1 < m) {
                    int4 v = p[e >> 1];
                    int p0 = atomicAdd(&s_cursor[v.x & 63], 1);
                    int p1 = atomicAdd(&s_cursor[v.z & 63], 1);
                    g_perm[p0] = lo + e;
                    g_perm[p1] = lo + e + 1;
                } else {
                    int t = (int)((const long long*)types)[lo + e];
                    g_perm[atomicAdd(&s_cursor[t & 63], 1)] = lo + e;
                }
            }
        } else {
            const int4* p = (const int4*)((const int*)types + lo);
            for (int e = tid * 4; e < m; e += 1024) {
                if (e + 3 < m) {
                    int4 v = p[e >> 2];
                    int p0 = atomicAdd(&s_cursor[v.x & 63], 1);
                    int p1 = atomicAdd(&s_cursor[v.y & 63], 1);
                    int p2 = atomicAdd(&s_cursor[v.z & 63], 1);
                    int p3 = atomicAdd(&s_cursor[v.w & 63], 1);
                    g_perm[p0] = lo + e;
                    g_perm[p1] = lo + e + 1;
                    g_perm[p2] = lo + e + 2;
                    g_perm[p3] = lo + e + 3;
                } else {
                    for (int j = e; j < m; j++) {
                        int t = ((const int*)types)[lo + j];
                        g_perm[atomicAdd(&s_cursor[t & 63], 1)] = lo + j;
                    }
                }
            }
        }
    }
}

// ---------------------------------------------------------------------------
// Kernel 2: GEMM. Block = 8 warps (4m x 2n), tile = 64 rows x 64 cols.
// k-slot permutation: MMA slot (tg, half) takes original k = 2*tg + half
// (applied identically to A and B -> result unchanged), making every
// fragment load an adjacent float2 (LDS.64), conflict-free at WSTR=72.
// ---------------------------------------------------------------------------
#define DSMEM_FLOATS (64 * WSTR + 64 + 128 + 2 * 64 * WSTR)
#define DSMEM_BYTES  (DSMEM_FLOATS * 4)

__global__ void __launch_bounds__(256, 4)
k_gemm(const float* __restrict__ x, const float* __restrict__ bias,
       float* __restrict__ out) {
    extern __shared__ float dsm[];
    float* Ws   = dsm;                       // [64][WSTR]: Ws[n][k] tf32 bits
    float* bsm  = Ws + 64 * WSTR;            // [64]
    int*   sidx = (int*)(bsm + 64);          // [2][64]
    float* As   = (float*)(sidx + 128);      // [2][64][WSTR]

    const int type  = blockIdx.y;
    const int seg0  = g_offsets[type];
    const int count = g_offsets[type + 1] - seg0;
    const int ntiles = (count + 63) >> 6;
    if ((int)blockIdx.x >= ntiles) return;

    const int tid = threadIdx.x;
    const int c   = tid & 15;    // float4 chunk within a row
    const int j0  = tid >> 4;    // row group

#define LOAD_STAGE(s, tile_)                                                  \
    do {                                                                      \
        float* dstb = As + (s) * 64 * WSTR;                                   \
        int t0 = (tile_) * 64;                                                \
        _Pragma("unroll")                                                     \
        for (int j = j0; j < 64; j += 16) {                                   \
            int r = t0 + j;                                                   \
            int valid = (r < count);                                          \
            int idx = valid ? __ldg(&g_perm[seg0 + r]) : 0;                   \
            if (c == 0) sidx[(s) * 64 + j] = valid ? idx : -1;                \
            uint32_t d = (uint32_t)__cvta_generic_to_shared(                  \
                dstb + j * WSTR + c * 4);                                     \
            cp_async16(d, x + (size_t)idx * 64 + c * 4);                      \
        }                                                                     \
    } while (0)

    // Stage 0: A gather + W + bias, one cp.async group.
    LOAD_STAGE(0, blockIdx.x);
    {
        const uint32_t* Wsrc = g_wtf + type * 4096;
#pragma unroll
        for (int q = 0; q < 4; q++) {
            int idx = q * 256 + tid;            // 1024 chunks of 16B
            int row = idx >> 4, cc = idx & 15;
            uint32_t d = (uint32_t)__cvta_generic_to_shared(
                Ws + row * WSTR + cc * 4);
            cp_async16(d, Wsrc + row * 64 + cc * 4);
        }
        if (tid < 16) {
            uint32_t d = (uint32_t)__cvta_generic_to_shared(bsm + tid * 4);
            cp_async16(d, bias + type * 64 + tid * 4);
        }
    }
    cp_commit();

    const int warp = tid >> 5;
    const int lane = tid & 31;
    const int wm = warp >> 1, wn = warp & 1;
    const int g  = lane >> 2, tg = lane & 3;
    const int lr0 = wm * 16 + g;

    int iter = 0;
    for (int tile = blockIdx.x; tile < ntiles; tile += gridDim.x, iter++) {
        const int s = iter & 1;
        const int nt = tile + gridDim.x;
        if (nt < ntiles) {
            LOAD_STAGE(s ^ 1, nt);
            cp_commit();
            cp_wait<1>();
        } else {
            cp_wait<0>();
        }
        __syncthreads();

        const float* A0 = As + s * 64 * WSTR + lr0 * WSTR + tg * 2;
        const float* A1 = A0 + 8 * WSTR;
        const float* Bbase = Ws + (wn * 32 + g) * WSTR + tg * 2;

        float acc[4][4];
#pragma unroll
        for (int nc = 0; nc < 4; nc++) {
            acc[nc][0] = 0.f; acc[nc][1] = 0.f;
            acc[nc][2] = 0.f; acc[nc][3] = 0.f;
        }

#pragma unroll
        for (int ks = 0; ks < 8; ks++) {
            float2 lo2 = *reinterpret_cast<const float2*>(A0 + ks * 8);
            float2 hi2 = *reinterpret_cast<const float2*>(A1 + ks * 8);
            uint32_t a[4];
            a[0] = f2tf32(lo2.x);   // row g,   k' = 2tg
            a[1] = f2tf32(hi2.x);   // row g+8, k' = 2tg
            a[2] = f2tf32(lo2.y);   // row g,   k' = 2tg+1
            a[3] = f2tf32(hi2.y);   // row g+8, k' = 2tg+1
#pragma unroll
            for (int nc = 0; nc < 4; nc++) {
                uint2 b2 = *reinterpret_cast<const uint2*>(
                    Bbase + nc * 8 * WSTR + ks * 8);
                mma_tf32(acc[nc], a, b2.x, b2.y);
            }
        }

        const int row0 = sidx[s * 64 + lr0];
        const int row1 = sidx[s * 64 + lr0 + 8];
#pragma unroll
        for (int nc = 0; nc < 4; nc++) {
            int col = wn * 32 + nc * 8 + tg * 2;
            float bv0 = bsm[col], bv1 = bsm[col + 1];
            if (row0 >= 0) {
                float2 v = make_float2(acc[nc][0] + bv0, acc[nc][1] + bv1);
                *reinterpret_cast<float2*>(out + (size_t)row0 * 64 + col) = v;
            }
            if (row1 >= 0) {
                float2 v = make_float2(acc[nc][2] + bv0, acc[nc][3] + bv1);
                *reinterpret_cast<float2*>(out + (size_t)row1 * 64 + col) = v;
            }
        }
        __syncthreads();
    }
#undef LOAD_STAGE
}

// ---------------------------------------------------------------------------
extern "C" void kernel_launch(void* const* d_in, const int* in_sizes, int n_in,
                              void* d_out, int out_size) {
    const float* x      = (const float*)d_in[0];
    const void*  types  = d_in[1];
    const float* matrix = (const float*)d_in[2];
    const float* bias   = (const float*)d_in[3];
    float*       out    = (float*)d_out;
    const int n = in_sizes[1];

    cudaFuncSetAttribute(k_gemm, cudaFuncAttributeMaxDynamicSharedMemorySize,
                         DSMEM_BYTES);

    k_sort<<<NB, 256>>>(types, matrix, n);
    dim3 grid(SLOTS, NUM_TYPES);
    k_gemm<<<grid, 256, DSMEM_BYTES>>>(x, bias, out);
}

// round 7
// speedup vs baseline: 1.6651x; 1.0094x over previous
#include <cuda_runtime.h>
#include <cuda_bf16.h>
#include <cstdint>

// AtomTypeLinear: out[n,:] = x[n,:] @ M[type[n]] + b[type[n]]
// N=100000, IN=OUT=64, NUM_TYPES=64, fp32.
//
// k_sort: fused histogram + grid barrier + scatter (counting sort)
//         + W transpose/convert to tf32 (g_wtf[type][n][k])
// k_gemm: per-type GEMM, mma.m16n8k8 tf32. A gathered via cp.async double
//         buffer (raw fp32 bits -> tf32 truncation, no cvt in mainloop).
//         Quad-k permutation makes every fragment load an LDS.128;
//         1-bit XOR swizzle keeps all smem accesses conflict-free.

#define NUM_TYPES 64
#define MAX_N     102400
#define NB        128     // sort blocks; co-resident (128 < 148 SMs)
#define SLOTS     9

__device__ int g_partialT[NUM_TYPES][NB];
__device__ int g_offsets[NUM_TYPES + 1];
__device__ int g_perm[MAX_N];
__device__ unsigned g_cnt = 0;
__device__ unsigned g_gen = 0;
__device__ uint32_t g_wtf[NUM_TYPES * 4096];   // tf32 bits, [type][n][k]

// ---------------------------------------------------------------------------
__device__ __forceinline__ uint32_t f2tf32(float f) {
    uint32_t r;
    asm("cvt.rna.tf32.f32 %0, %1;" : "=r"(r) : "f"(f));
    return r;
}

__device__ __forceinline__ void mma_tf32(float* c,
                                         uint32_t a0, uint32_t a1,
                                         uint32_t a2, uint32_t a3,
                                         uint32_t b0, uint32_t b1) {
    asm volatile(
        "mma.sync.aligned.m16n8k8.row.col.f32.tf32.tf32.f32 "
        "{%0,%1,%2,%3}, {%4,%5,%6,%7}, {%8,%9}, {%0,%1,%2,%3};"
        : "+f"(c[0]), "+f"(c[1]), "+f"(c[2]), "+f"(c[3])
        : "r"(a0), "r"(a1), "r"(a2), "r"(a3), "r"(b0), "r"(b1));
}

__device__ __forceinline__ void cp_async16(uint32_t dst, const void* src) {
    asm volatile("cp.async.ca.shared.global [%0], [%1], 16;" :: "r"(dst), "l"(src));
}
__device__ __forceinline__ void cp_commit() {
    asm volatile("cp.async.commit_group;");
}
template <int N>
__device__ __forceinline__ void cp_wait() {
    asm volatile("cp.async.wait_group %0;" :: "n"(N));
}

// Sense-reversing grid barrier; all NB blocks co-resident in wave 1.
__device__ __forceinline__ void grid_barrier() {
    __threadfence();
    __syncthreads();
    if (threadIdx.x == 0) {
        unsigned gen = atomicAdd(&g_gen, 0u);
        __threadfence();
        if (atomicAdd(&g_cnt, 1u) == (unsigned)NB - 1u) {
            atomicExch(&g_cnt, 0u);
            __threadfence();
            atomicAdd(&g_gen, 1u);
        } else {
            while (atomicAdd(&g_gen, 0u) == gen) {}
        }
    }
    __syncthreads();
}

// ---------------------------------------------------------------------------
// Kernel 1: fused counting sort + W transpose/convert.
// ---------------------------------------------------------------------------
__global__ void __launch_bounds__(256)
k_sort(const void* __restrict__ types, const float* __restrict__ Wm, int n) {
    __shared__ int sh[NUM_TYPES];
    __shared__ int s_is64;
    __shared__ int s_wtot[4][NUM_TYPES];
    __shared__ int s_wbef[4][NUM_TYPES];
    __shared__ int s_off[NUM_TYPES];
    __shared__ int s_cursor[NUM_TYPES];
    __shared__ float sW[32][65];

    const int tid = threadIdx.x;
    const int b   = blockIdx.x;

    if (tid < NUM_TYPES) sh[tid] = 0;
    if (tid == 0) s_is64 = 1;
    __syncthreads();
    // int64 (LE) => every odd 32-bit word is 0 (values < 64).
    if (tid < 64) {
        int idx = 2 * tid + 1;
        if (idx < n && ((const int*)types)[idx] != 0) s_is64 = 0;
    }
    __syncthreads();
    const int is64 = s_is64;

    const int chunk = (((n + NB - 1) / NB) + 3) & ~3;
    const int lo = b * chunk;
    const int hi = min(n, lo + chunk);
    const int m  = hi - lo;

    // --- phase A: histogram ---
    if (m > 0) {
        if (is64) {
            const int4* p = (const int4*)((const long long*)types + lo);
            for (int e = tid * 2; e < m; e += 512) {
                if (e + 1 < m) {
                    int4 v = p[e >> 1];
                    atomicAdd(&sh[v.x & 63], 1);
                    atomicAdd(&sh[v.z & 63], 1);
                } else {
                    int t = (int)((const long long*)types)[lo + e];
                    atomicAdd(&sh[t & 63], 1);
                }
            }
        } else {
            const int4* p = (const int4*)((const int*)types + lo);
            for (int e = tid * 4; e < m; e += 1024) {
                if (e + 3 < m) {
                    int4 v = p[e >> 2];
                    atomicAdd(&sh[v.x & 63], 1);
                    atomicAdd(&sh[v.y & 63], 1);
                    atomicAdd(&sh[v.z & 63], 1);
                    atomicAdd(&sh[v.w & 63], 1);
                } else {
                    for (int j = e; j < m; j++)
                        atomicAdd(&sh[((const int*)types)[lo + j] & 63], 1);
                }
            }
        }
    }
    __syncthreads();
    if (tid < NUM_TYPES) g_partialT[tid][b] = sh[tid];

    // --- W transpose + tf32 convert (overlaps barrier wait) ---
    {
        const int ty = b >> 1;
        const int k0 = (b & 1) * 32;
        const float* Wt = Wm + ty * 4096 + k0 * 64;   // [32 rows][64 n]
        for (int idx = tid; idx < 2048; idx += 256)
            sW[idx >> 6][idx & 63] = Wt[idx];          // coalesced read
        __syncthreads();
        for (int idx = tid; idx < 2048; idx += 256) {
            int nn = idx >> 5, kk = idx & 31;
            g_wtf[ty * 4096 + nn * 64 + k0 + kk] = f2tf32(sW[kk][nn]);
        }
    }

    grid_barrier();

    // --- phase B: reconstruct cursors (coalesced int4 reduction) ---
    {
        const int q = tid >> 6;       // window of 32 blocks
        const int t = tid & 63;
        const int b0w = q * 32;
        const int4* row = (const int4*)&g_partialT[t][b0w];
        int tot = 0, bef = 0;
#pragma unroll
        for (int i = 0; i < 8; i++) {
            int4 v = row[i];
            int bb = b0w + i * 4;
            tot += v.x + v.y + v.z + v.w;
            if (bb + 0 < b) bef += v.x;
            if (bb + 1 < b) bef += v.y;
            if (bb + 2 < b) bef += v.z;
            if (bb + 3 < b) bef += v.w;
        }
        s_wtot[q][t] = tot;
        s_wbef[q][t] = bef;
    }
    __syncthreads();
    if (tid < NUM_TYPES) {
        s_wtot[0][tid] = s_wtot[0][tid] + s_wtot[1][tid] + s_wtot[2][tid] + s_wtot[3][tid];
        s_wbef[0][tid] = s_wbef[0][tid] + s_wbef[1][tid] + s_wbef[2][tid] + s_wbef[3][tid];
    }
    __syncthreads();
    if (tid == 0) {
        int acc = 0;
        for (int t = 0; t < NUM_TYPES; t++) {
            s_off[t] = acc;
            acc += s_wtot[0][t];
        }
    }
    __syncthreads();
    if (tid < NUM_TYPES) {
        s_cursor[tid] = s_off[tid] + s_wbef[0][tid];
        if (b == 0) g_offsets[tid] = s_off[tid];
    }
    if (b == 0 && tid == 0) g_offsets[NUM_TYPES] = n;
    __syncthreads();

    // --- scatter ---
    if (m > 0) {
        if (is64) {
            const int4* p = (const int4*)((const long long*)types + lo);
            for (int e = tid * 2; e < m; e += 512) {
                if (e + 1 < m) {
                    int4 v = p[e >> 1];
                    int p0 = atomicAdd(&s_cursor[v.x & 63], 1);
                    int p1 = atomicAdd(&s_cursor[v.z & 63], 1);
                    g_perm[p0] = lo + e;
                    g_perm[p1] = lo + e + 1;
                } else {
                    int t = (int)((const long long*)types)[lo + e];
                    g_perm[atomicAdd(&s_cursor[t & 63], 1)] = lo + e;
                }
            }
        } else {
            const int4* p = (const int4*)((const int*)types + lo);
            for (int e = tid * 4; e < m; e += 1024) {
                if (e + 3 < m) {
                    int4 v = p[e >> 2];
                    int p0 = atomicAdd(&s_cursor[v.x & 63], 1);
                    int p1 = atomicAdd(&s_cursor[v.y & 63], 1);
                    int p2 = atomicAdd(&s_cursor[v.z & 63], 1);
                    int p3 = atomicAdd(&s_cursor[v.w & 63], 1);
                    g_perm[p0] = lo + e;
                    g_perm[p1] = lo + e + 1;
                    g_perm[p2] = lo + e + 2;
                    g_perm[p3] = lo + e + 3;
                } else {
                    for (int j = e; j < m; j++) {
                        int t = ((const int*)types)[lo + j];
                        g_perm[atomicAdd(&s_cursor[t & 63], 1)] = lo + j;
                    }
                }
            }
        }
    }
}

// ---------------------------------------------------------------------------
// Kernel 2: GEMM. Block = 8 warps (4m x 2n), tile = 64 rows x 64 cols.
// Quad-k permutation: MMA pair (j, p), slot s -> k = 16j + 4(s%4) + 2(s/4) + p
// (A and B use the same map -> result unchanged). Each thread's 4 k-values
// per row per j are contiguous -> LDS.128. Layout: rows of 64 floats,
// 16B-chunk index XOR'd with (row&1)<<2 -> conflict-free 128-bit accesses.
// A is fed as raw fp32 bits (tf32 truncation); W pre-converted with rna.
// ---------------------------------------------------------------------------
#define DSMEM_FLOATS (4096 + 64 + 128 + 2 * 4096)
#define DSMEM_BYTES  (DSMEM_FLOATS * 4)

__global__ void __launch_bounds__(256, 4)
k_gemm(const float* __restrict__ x, const float* __restrict__ bias,
       float* __restrict__ out) {
    extern __shared__ float dsm[];
    float* Ws   = dsm;                       // [64 cols][64 k] swizzled
    float* bsm  = Ws + 4096;                 // [64]
    int*   sidx = (int*)(bsm + 64);          // [2][64]
    float* As   = (float*)(sidx + 128);      // [2][64 rows][64 k] swizzled

    const int type  = blockIdx.y;
    const int seg0  = g_offsets[type];
    const int count = g_offsets[type + 1] - seg0;
    const int ntiles = (count + 63) >> 6;
    if ((int)blockIdx.x >= ntiles) return;

    const int tid = threadIdx.x;
    const int c   = tid & 15;    // 16B chunk within a row
    const int j0  = tid >> 4;    // row group

#define LOAD_STAGE(s, tile_)                                                  \
    do {                                                                      \
        float* dstb = As + (s) * 4096;                                        \
        int t0 = (tile_) * 64;                                                \
        _Pragma("unroll")                                                     \
        for (int j = j0; j < 64; j += 16) {                                   \
            int r = t0 + j;                                                   \
            int valid = (r < count);                                          \
            int idx = valid ? __ldg(&g_perm[seg0 + r]) : 0;                   \
            if (c == 0) sidx[(s) * 64 + j] = valid ? idx : -1;                \
            int pc = c ^ ((j & 1) << 2);                                      \
            uint32_t d = (uint32_t)__cvta_generic_to_shared(                  \
                dstb + j * 64 + pc * 4);                                      \
            cp_async16(d, x + (size_t)idx * 64 + c * 4);                      \
        }                                                                     \
    } while (0)

    // Stage 0: A gather + W + bias, one cp.async group.
    LOAD_STAGE(0, blockIdx.x);
    {
        const uint32_t* Wsrc = g_wtf + type * 4096;
#pragma unroll
        for (int q = 0; q < 4; q++) {
            int idx = q * 256 + tid;            // 1024 chunks of 16B
            int row = idx >> 4, cc = idx & 15;
            int pc = cc ^ ((row & 1) << 2);
            uint32_t d = (uint32_t)__cvta_generic_to_shared(
                Ws + row * 64 + pc * 4);
            cp_async16(d, Wsrc + row * 64 + cc * 4);
        }
        if (tid < 16) {
            uint32_t d = (uint32_t)__cvta_generic_to_shared(bsm + tid * 4);
            cp_async16(d, bias + type * 64 + tid * 4);
        }
    }
    cp_commit();

    const int warp = tid >> 5;
    const int lane = tid & 31;
    const int wm = warp >> 1, wn = warp & 1;
    const int g  = lane >> 2, tg = lane & 3;
    const int lr0 = wm * 16 + g;
    const int sw = (g & 1) << 2;   // XOR swizzle (row/col parity == g parity)

    int iter = 0;
    for (int tile = blockIdx.x; tile < ntiles; tile += gridDim.x, iter++) {
        const int s = iter & 1;
        const int nt = tile + gridDim.x;
        if (nt < ntiles) {
            LOAD_STAGE(s ^ 1, nt);
            cp_commit();
            cp_wait<1>();
        } else {
            cp_wait<0>();
        }
        __syncthreads();

        const uint4* A0 = (const uint4*)(As + s * 4096 + lr0 * 64);
        const uint4* A1 = (const uint4*)(As + s * 4096 + (lr0 + 8) * 64);
        const uint4* B0 = (const uint4*)(Ws + (wn * 32 + g) * 64);

        float acc[4][4];
#pragma unroll
        for (int nc = 0; nc < 4; nc++) {
            acc[nc][0] = 0.f; acc[nc][1] = 0.f;
            acc[nc][2] = 0.f; acc[nc][3] = 0.f;
        }

#pragma unroll
        for (int j = 0; j < 4; j++) {
            const int cidx = (4 * j + tg) ^ sw;
            uint4 ar0 = A0[cidx];
            uint4 ar1 = A1[cidx];
#pragma unroll
            for (int nc = 0; nc < 4; nc++) {
                uint4 b4 = B0[nc * 128 + cidx];   // nc*8 cols * 16 chunks
                mma_tf32(acc[nc], ar0.x, ar1.x, ar0.z, ar1.z, b4.x, b4.z);
                mma_tf32(acc[nc], ar0.y, ar1.y, ar0.w, ar1.w, b4.y, b4.w);
            }
        }

        const int row0 = sidx[s * 64 + lr0];
        const int row1 = sidx[s * 64 + lr0 + 8];
#pragma unroll
        for (int nc = 0; nc < 4; nc++) {
            int col = wn * 32 + nc * 8 + tg * 2;
            float bv0 = bsm[col], bv1 = bsm[col + 1];
            if (row0 >= 0) {
                float2 v = make_float2(acc[nc][0] + bv0, acc[nc][1] + bv1);
                *reinterpret_cast<float2*>(out + (size_t)row0 * 64 + col) = v;
            }
            if (row1 >= 0) {
                float2 v = make_float2(acc[nc][2] + bv0, acc[nc][3] + bv1);
                *reinterpret_cast<float2*>(out + (size_t)row1 * 64 + col) = v;
            }
        }
        __syncthreads();
    }
#undef LOAD_STAGE
}

// ---------------------------------------------------------------------------
extern "C" void kernel_launch(void* const* d_in, const int* in_sizes, int n_in,
                              void* d_out, int out_size) {
    const float* x      = (const float*)d_in[0];
    const void*  types  = d_in[1];
    const float* matrix = (const float*)d_in[2];
    const float* bias   = (const float*)d_in[3];
    float*       out    = (float*)d_out;
    const int n = in_sizes[1];

    cudaFuncSetAttribute(k_gemm, cudaFuncAttributeMaxDynamicSharedMemorySize,
                         DSMEM_BYTES);

    k_sort<<<NB, 256>>>(types, matrix, n);
    dim3 grid(SLOTS, NUM_TYPES);
    k_gemm<<<grid, 256, DSMEM_BYTES>>>(x, bias, out);
}